// round 13
// baseline (speedup 1.0000x reference)
#include <cuda_runtime.h>
#include <cuda_fp16.h>
#include <mma.h>
#include <math.h>

#define N_NODES 100000
#define N_EDGES 1600000
#define N_GRAPHS 64
#define NEG_SLOPE 0.2f
#define SCAN_BLK 256
#define N_SCAN_BLKS ((N_NODES + SCAN_BLK - 1) / SCAN_BLK)   // 391
#define CHUNK 50048          // node split for pipelining (multiple of 64 and 8)

// ---------------- static scratch (no allocs allowed) ----------------
__device__ __half g_bufH [N_NODES * 128];  // layer-1 h / layer-3 h (fp16)
__device__ __half g_bufH2[N_NODES * 128];  // layer-2 h (fp16)
__device__ __half g_xH   [N_NODES * 128];  // agg outputs (relu'd fp16, next GEMM's A)
__device__ float  g_ssrc [N_NODES * 4];    // layer-1/3 scores
__device__ float  g_sdst [N_NODES * 4];
__device__ float  g_ssrc2[N_NODES * 4];    // layer-2 scores
__device__ float  g_sdst2[N_NODES * 4];
__device__ float  g_pool[N_GRAPHS * 8];
__device__ float  g_cnt [N_GRAPHS];
// CSR (dst-sorted incoming edges)
__device__ int g_rowptr[N_NODES + 1];
__device__ int g_fill  [N_NODES];
__device__ int g_srcsorted[N_EDGES];
__device__ int g_bsum[512];

__device__ __forceinline__ float lrelu(float x) { return x > 0.f ? x : NEG_SLOPE * x; }

__device__ __forceinline__ void ldh8f(const __half* p, float* o) {
    uint4 r = *reinterpret_cast<const uint4*>(p);
    float2 a = __half22float2(*reinterpret_cast<__half2*>(&r.x));
    float2 b = __half22float2(*reinterpret_cast<__half2*>(&r.y));
    float2 c = __half22float2(*reinterpret_cast<__half2*>(&r.z));
    float2 d = __half22float2(*reinterpret_cast<__half2*>(&r.w));
    o[0] = a.x; o[1] = a.y; o[2] = b.x; o[3] = b.y;
    o[4] = c.x; o[5] = c.y; o[6] = d.x; o[7] = d.y;
}

// ================= CSR build =================
__global__ void csr_zero_fill() {
    int i = blockIdx.x * blockDim.x + threadIdx.x;
    if (i < N_NODES) g_fill[i] = 0;
}

__global__ void csr_hist(const int* __restrict__ ei) {
    int e = blockIdx.x * blockDim.x + threadIdx.x;
    if (e < N_EDGES) atomicAdd(&g_fill[ei[N_EDGES + e]], 1);
}

__global__ void csr_scan1() {
    __shared__ int sh[SCAN_BLK];
    int t = threadIdx.x;
    int i = blockIdx.x * SCAN_BLK + t;
    int v = (i < N_NODES) ? g_fill[i] : 0;
    sh[t] = v;
    __syncthreads();
#pragma unroll
    for (int off = 1; off < SCAN_BLK; off <<= 1) {
        int add = (t >= off) ? sh[t - off] : 0;
        __syncthreads();
        sh[t] += add;
        __syncthreads();
    }
    if (i < N_NODES) g_rowptr[i] = sh[t] - v;
    if (t == SCAN_BLK - 1) g_bsum[blockIdx.x] = sh[t];
}

__global__ void csr_scan2() {
    __shared__ int sh[512];
    int t = threadIdx.x;
    int v = (t < N_SCAN_BLKS) ? g_bsum[t] : 0;
    sh[t] = v;
    __syncthreads();
#pragma unroll
    for (int off = 1; off < 512; off <<= 1) {
        int add = (t >= off) ? sh[t - off] : 0;
        __syncthreads();
        sh[t] += add;
        __syncthreads();
    }
    if (t < N_SCAN_BLKS) g_bsum[t] = sh[t] - v;
}

__global__ void csr_scan3() {
    int i = blockIdx.x * blockDim.x + threadIdx.x;
    if (i < N_NODES) {
        g_rowptr[i] += g_bsum[i >> 8];
        g_fill[i] = 0;
    }
    if (i == 0) g_rowptr[N_NODES] = N_EDGES;
}

__global__ void csr_scatter(const int* __restrict__ ei) {
    int e = blockIdx.x * blockDim.x + threadIdx.x;
    if (e >= N_EDGES) return;
    int d = ei[N_EDGES + e];
    int pos = g_rowptr[d] + atomicAdd(&g_fill[d], 1);
    g_srcsorted[pos] = ei[e];
}

// ================= WMMA GEMM + score epilogue (chunked by node base) =================
template<int K, int N, int H, int C, typename TIN>
__global__ void __launch_bounds__(128) gemm_wmma(
    const TIN* __restrict__ xin, const float* __restrict__ W,
    const float* __restrict__ asrc, const float* __restrict__ adst,
    __half* __restrict__ hout, float* __restrict__ ssrc, float* __restrict__ sdst,
    int nbase)
{
    using namespace nvcuda;
    constexpr int KS  = K + 8;
    constexpr int NS  = N + 8;
    constexpr int NSF = N + 8;
    constexpr int NT  = N / 16;
    constexpr int KT  = K / 16;
    constexpr int ASZ = 64 * KS * 2;
    constexpr int BSZ = K * NS * 2;
    constexpr int CSZ = 64 * NSF * 4;
    constexpr int SMB = (ASZ + BSZ) > CSZ ? (ASZ + BSZ) : CSZ;
    __shared__ __align__(16) char smem[SMB];
    __half* As = reinterpret_cast<__half*>(smem);
    __half* Bs = reinterpret_cast<__half*>(smem + ASZ);
    float*  Cs = reinterpret_cast<float*>(smem);

    const int m0blk = nbase + blockIdx.x * 64;

    // ---- stage A ----
    {
        constexpr int CH = 64 * (K / 8);
        for (int c = threadIdx.x; c < CH; c += 128) {
            int rl = c / (K / 8);
            int kc = (c % (K / 8)) * 8;
            int row = min(m0blk + rl, N_NODES - 1);
            uint4 pk;
            if (sizeof(TIN) == 4) {
                const float4* p = reinterpret_cast<const float4*>((const float*)xin + (size_t)row * K + kc);
                float4 v0 = p[0], v1 = p[1];
                __half2 h0 = __floats2half2_rn(v0.x, v0.y);
                __half2 h1 = __floats2half2_rn(v0.z, v0.w);
                __half2 h2 = __floats2half2_rn(v1.x, v1.y);
                __half2 h3 = __floats2half2_rn(v1.z, v1.w);
                pk.x = *reinterpret_cast<unsigned*>(&h0);
                pk.y = *reinterpret_cast<unsigned*>(&h1);
                pk.z = *reinterpret_cast<unsigned*>(&h2);
                pk.w = *reinterpret_cast<unsigned*>(&h3);
            } else {
                pk = *reinterpret_cast<const uint4*>((const __half*)xin + (size_t)row * K + kc);
            }
            *reinterpret_cast<uint4*>(&As[rl * KS + kc]) = pk;
        }
    }
    // ---- stage B ----
    {
        constexpr int CH = K * (N / 8);
        for (int c = threadIdx.x; c < CH; c += 128) {
            int k  = c / (N / 8);
            int nc = (c % (N / 8)) * 8;
            const float4* p = reinterpret_cast<const float4*>(W + (size_t)k * N + nc);
            float4 v0 = p[0], v1 = p[1];
            __half2 h0 = __floats2half2_rn(v0.x, v0.y);
            __half2 h1 = __floats2half2_rn(v0.z, v0.w);
            __half2 h2 = __floats2half2_rn(v1.x, v1.y);
            __half2 h3 = __floats2half2_rn(v1.z, v1.w);
            uint4 pk;
            pk.x = *reinterpret_cast<unsigned*>(&h0);
            pk.y = *reinterpret_cast<unsigned*>(&h1);
            pk.z = *reinterpret_cast<unsigned*>(&h2);
            pk.w = *reinterpret_cast<unsigned*>(&h3);
            *reinterpret_cast<uint4*>(&Bs[k * NS + nc]) = pk;
        }
    }
    __syncthreads();

    const int warp = threadIdx.x >> 5;

    wmma::fragment<wmma::accumulator, 16, 16, 16, float> acc[NT];
#pragma unroll
    for (int nt = 0; nt < NT; nt++) wmma::fill_fragment(acc[nt], 0.f);

#pragma unroll
    for (int kt = 0; kt < KT; kt++) {
        wmma::fragment<wmma::matrix_a, 16, 16, 16, __half, wmma::row_major> af;
        wmma::load_matrix_sync(af, As + (warp * 16) * KS + kt * 16, KS);
#pragma unroll
        for (int nt = 0; nt < NT; nt++) {
            wmma::fragment<wmma::matrix_b, 16, 16, 16, __half, wmma::row_major> bf;
            wmma::load_matrix_sync(bf, Bs + (kt * 16) * NS + nt * 16, NS);
            wmma::mma_sync(acc[nt], af, bf, acc[nt]);
        }
    }

    __syncthreads();
#pragma unroll
    for (int nt = 0; nt < NT; nt++)
        wmma::store_matrix_sync(Cs + (warp * 16) * NSF + nt * 16, acc[nt], NSF, wmma::mem_row_major);
    __syncthreads();

    // ---- epilogue: 2 threads per row, each owns N/2 cols = whole heads ----
    {
        constexpr int HALF = N / 2;
        constexpr int HH   = (H >= 2) ? H / 2 : 1;
        const int row  = threadIdx.x & 63;
        const int half = threadIdx.x >> 6;
        const int n    = m0blk + row;
        if (n < N_NODES) {
            const int c0 = half * HALF;
            const float* cr = Cs + row * NSF + c0;
            float sc[HH], dc[HH];
#pragma unroll
            for (int hh = 0; hh < HH; hh++) { sc[hh] = 0.f; dc[hh] = 0.f; }
#pragma unroll
            for (int i = 0; i < HALF; i += 8) {
                float4 v0 = *reinterpret_cast<const float4*>(cr + i);
                float4 v1 = *reinterpret_cast<const float4*>(cr + i + 4);
                int hh = i / C;
                sc[hh] += v0.x * asrc[c0 + i + 0] + v0.y * asrc[c0 + i + 1]
                        + v0.z * asrc[c0 + i + 2] + v0.w * asrc[c0 + i + 3]
                        + v1.x * asrc[c0 + i + 4] + v1.y * asrc[c0 + i + 5]
                        + v1.z * asrc[c0 + i + 6] + v1.w * asrc[c0 + i + 7];
                dc[hh] += v0.x * adst[c0 + i + 0] + v0.y * adst[c0 + i + 1]
                        + v0.z * adst[c0 + i + 2] + v0.w * adst[c0 + i + 3]
                        + v1.x * adst[c0 + i + 4] + v1.y * adst[c0 + i + 5]
                        + v1.z * adst[c0 + i + 6] + v1.w * adst[c0 + i + 7];
                __half2 p0 = __floats2half2_rn(v0.x, v0.y);
                __half2 p1 = __floats2half2_rn(v0.z, v0.w);
                __half2 p2 = __floats2half2_rn(v1.x, v1.y);
                __half2 p3 = __floats2half2_rn(v1.z, v1.w);
                uint4 pk;
                pk.x = *reinterpret_cast<unsigned*>(&p0);
                pk.y = *reinterpret_cast<unsigned*>(&p1);
                pk.z = *reinterpret_cast<unsigned*>(&p2);
                pk.w = *reinterpret_cast<unsigned*>(&p3);
                *reinterpret_cast<uint4*>(&hout[(size_t)n * N + c0 + i]) = pk;
            }
            const int hb = half * HH;
#pragma unroll
            for (int hh = 0; hh < HH; hh++) {
                ssrc[n * H + hb + hh] = sc[hh];
                sdst[n * H + hb + hh] = dc[hh];
            }
        }
    }
}

// ================= layer-3 GEMM (HC=8, scalar, fp16 input, chunked) =================
__global__ void gemm_score_l3(const __half* __restrict__ x, const float* __restrict__ W,
                              const float* __restrict__ asrc, const float* __restrict__ adst,
                              __half* __restrict__ hout, float* __restrict__ ssrc,
                              float* __restrict__ sdst, int nbase)
{
    constexpr int K = 128, HC = 8, TPN = 2, NB = 64, TPB = 128;
    __shared__ float xs[NB * K];

    const int base = nbase + blockIdx.x * NB;
    for (int i = threadIdx.x; i < NB * K; i += TPB) {
        int n = base + i / K;
        xs[i] = (n < N_NODES) ? __half2float(x[(size_t)n * K + (i % K)]) : 0.f;
    }
    __syncthreads();

    const int local = threadIdx.x / TPN;
    const int tj    = threadIdx.x % TPN;
    const int j0    = tj * 4;
    const int n     = base + local;
    if (n >= N_NODES) return;

    const float* xr = &xs[local * K];
    const float4* W4 = reinterpret_cast<const float4*>(W);
    float a0 = 0.f, a1 = 0.f, a2 = 0.f, a3 = 0.f;
#pragma unroll 8
    for (int k = 0; k < K; k++) {
        float xv = xr[k];
        float4 wv = W4[k * TPN + tj];
        a0 = fmaf(xv, wv.x, a0);
        a1 = fmaf(xv, wv.y, a1);
        a2 = fmaf(xv, wv.z, a2);
        a3 = fmaf(xv, wv.w, a3);
    }

    {
        __half2 lo = __floats2half2_rn(a0, a1);
        __half2 hi = __floats2half2_rn(a2, a3);
        uint2 pk;
        pk.x = *reinterpret_cast<unsigned*>(&lo);
        pk.y = *reinterpret_cast<unsigned*>(&hi);
        *reinterpret_cast<uint2*>(&hout[(size_t)n * HC + j0]) = pk;
    }

    float vs = a0 * asrc[j0] + a1 * asrc[j0 + 1] + a2 * asrc[j0 + 2] + a3 * asrc[j0 + 3];
    float vd = a0 * adst[j0] + a1 * adst[j0 + 1] + a2 * adst[j0 + 2] + a3 * adst[j0 + 3];
    vs += __shfl_down_sync(0xffffffffu, vs, 1);
    vd += __shfl_down_sync(0xffffffffu, vd, 1);
    if (tj == 0) {
        ssrc[n] = vs;
        sdst[n] = vd;
    }
}

// ================= CSR aggregation: warp per node, chunked, 4-deep MLP =================
template<int H, int C>
__global__ void csr_aggN(const float* __restrict__ ssrc, const float* __restrict__ sdst,
                         const __half* __restrict__ hbuf, const float* __restrict__ bias,
                         __half* __restrict__ out, int nbase, int nend)
{
    constexpr int HC   = H * C;           // 64 or 128
    constexpr int LPE  = HC / 8;          // lanes per edge: 8 or 16
    constexpr int NSUB = 32 / LPE;        // 4 or 2
    int n = nbase + blockIdx.x * (blockDim.x / 32) + (threadIdx.x >> 5);
    if (n >= nend) return;
    int lane = threadIdx.x & 31;
    int sub  = lane / LPE;
    int cpos = lane % LPE;
    int j0   = cpos * 8;
    int h    = j0 / C;

    const float sds = sdst[n * H + h];
    float acc[8];
#pragma unroll
    for (int v = 0; v < 8; v++) acc[v] = 0.f;
    float den = 0.f;
    if (sub == 0) {
        float wself = __expf(lrelu(ssrc[n * H + h] + sds));
        den = wself;
        float hv[8];
        ldh8f(&hbuf[(size_t)n * HC + j0], hv);
#pragma unroll
        for (int v = 0; v < 8; v++) acc[v] = wself * hv[v];
    }

    int e   = g_rowptr[n];
    int end = g_rowptr[n + 1];
    // 4-deep main loop: 4 independent gathers in flight per lane
    for (; e + 4 * NSUB - 1 < end; e += 4 * NSUB) {
        int sA = g_srcsorted[e + sub];
        int sB = g_srcsorted[e + NSUB + sub];
        int sC = g_srcsorted[e + 2 * NSUB + sub];
        int sD = g_srcsorted[e + 3 * NSUB + sub];
        float wA = __expf(lrelu(ssrc[sA * H + h] + sds));
        float wB = __expf(lrelu(ssrc[sB * H + h] + sds));
        float wC = __expf(lrelu(ssrc[sC * H + h] + sds));
        float wD = __expf(lrelu(ssrc[sD * H + h] + sds));
        float hA[8], hB[8], hC[8], hD[8];
        ldh8f(&hbuf[(size_t)sA * HC + j0], hA);
        ldh8f(&hbuf[(size_t)sB * HC + j0], hB);
        ldh8f(&hbuf[(size_t)sC * HC + j0], hC);
        ldh8f(&hbuf[(size_t)sD * HC + j0], hD);
#pragma unroll
        for (int v = 0; v < 8; v++)
            acc[v] += (wA * hA[v] + wB * hB[v]) + (wC * hC[v] + wD * hD[v]);
        den += (wA + wB) + (wC + wD);
    }
    // 2-deep
    for (; e + 2 * NSUB - 1 < end; e += 2 * NSUB) {
        int sA = g_srcsorted[e + sub];
        int sB = g_srcsorted[e + NSUB + sub];
        float wA = __expf(lrelu(ssrc[sA * H + h] + sds));
        float wB = __expf(lrelu(ssrc[sB * H + h] + sds));
        float hA[8], hB[8];
        ldh8f(&hbuf[(size_t)sA * HC + j0], hA);
        ldh8f(&hbuf[(size_t)sB * HC + j0], hB);
#pragma unroll
        for (int v = 0; v < 8; v++) acc[v] += wA * hA[v] + wB * hB[v];
        den += wA + wB;
    }
    // predicated tail
    for (; e < end; e += NSUB) {
        int idx    = e + sub;
        bool valid = idx < end;
        int s = g_srcsorted[valid ? idx : e];
        float w = valid ? __expf(lrelu(ssrc[s * H + h] + sds)) : 0.f;
        float hv[8];
        ldh8f(&hbuf[(size_t)s * HC + j0], hv);
#pragma unroll
        for (int v = 0; v < 8; v++) acc[v] += w * hv[v];
        den += w;
    }

#pragma unroll
    for (int off = LPE; off < 32; off <<= 1) {
#pragma unroll
        for (int v = 0; v < 8; v++) acc[v] += __shfl_xor_sync(0xffffffffu, acc[v], off);
        den += __shfl_xor_sync(0xffffffffu, den, off);
    }

    if (sub == 0) {
        float inv = 1.f / den;
        float r[8];
#pragma unroll
        for (int v = 0; v < 8; v++) r[v] = fmaxf(acc[v] * inv + bias[j0 + v], 0.f);
        __half2 p0 = __floats2half2_rn(r[0], r[1]);
        __half2 p1 = __floats2half2_rn(r[2], r[3]);
        __half2 p2 = __floats2half2_rn(r[4], r[5]);
        __half2 p3 = __floats2half2_rn(r[6], r[7]);
        uint4 pk;
        pk.x = *reinterpret_cast<unsigned*>(&p0);
        pk.y = *reinterpret_cast<unsigned*>(&p1);
        pk.z = *reinterpret_cast<unsigned*>(&p2);
        pk.w = *reinterpret_cast<unsigned*>(&p3);
        *reinterpret_cast<uint4*>(&out[(size_t)n * HC + j0]) = pk;
    }
}

// ================= Layer 3: thread-per-node (HC=8), fused into pooling =================
__global__ void csr_agg_t8_pool(const float* __restrict__ ssrc, const float* __restrict__ sdst,
                                const __half* __restrict__ hbuf, const float* __restrict__ bias,
                                const int* __restrict__ batch)
{
    int n = blockIdx.x * blockDim.x + threadIdx.x;
    if (n >= N_NODES) return;
    const float sds   = sdst[n];
    const float wself = __expf(lrelu(ssrc[n] + sds));

    float a[8], hv[8];
    ldh8f(&hbuf[(size_t)n * 8], hv);
#pragma unroll
    for (int v = 0; v < 8; v++) a[v] = wself * hv[v];
    float den = wself;

    int e = g_rowptr[n], end = g_rowptr[n + 1];
    for (; e + 3 < end; e += 4) {
        int s0 = g_srcsorted[e],     s1 = g_srcsorted[e + 1];
        int s2 = g_srcsorted[e + 2], s3 = g_srcsorted[e + 3];
        float w0 = __expf(lrelu(ssrc[s0] + sds));
        float w1 = __expf(lrelu(ssrc[s1] + sds));
        float w2 = __expf(lrelu(ssrc[s2] + sds));
        float w3 = __expf(lrelu(ssrc[s3] + sds));
        float h0[8], h1[8], h2[8], h3[8];
        ldh8f(&hbuf[(size_t)s0 * 8], h0);
        ldh8f(&hbuf[(size_t)s1 * 8], h1);
        ldh8f(&hbuf[(size_t)s2 * 8], h2);
        ldh8f(&hbuf[(size_t)s3 * 8], h3);
#pragma unroll
        for (int v = 0; v < 8; v++)
            a[v] += (w0 * h0[v] + w1 * h1[v]) + (w2 * h2[v] + w3 * h3[v]);
        den += (w0 + w1) + (w2 + w3);
    }
    for (; e < end; e++) {
        int s = g_srcsorted[e];
        float w = __expf(lrelu(ssrc[s] + sds));
        ldh8f(&hbuf[(size_t)s * 8], hv);
#pragma unroll
        for (int v = 0; v < 8; v++) a[v] += w * hv[v];
        den += w;
    }
    float inv = 1.f / den;
    int g = batch[n];
    float* pp = &g_pool[g * 8];
#pragma unroll
    for (int v = 0; v < 8; v++) atomicAdd(pp + v, a[v] * inv + bias[v]);
    atomicAdd(&g_cnt[g], 1.f);
}

// ================= pooling epilogue =================
__global__ void pool_zero() {
    int i = blockIdx.x * blockDim.x + threadIdx.x;
    if (i < N_GRAPHS * 8) g_pool[i] = 0.f;
    if (i < N_GRAPHS)     g_cnt[i]  = 0.f;
}

__global__ void pool_out(float* __restrict__ out)
{
    int i = threadIdx.x;
    if (i < N_GRAPHS * 8) {
        float v = g_pool[i] / fmaxf(g_cnt[i / 8], 1.f);
        out[i] = 1.f / (1.f + expf(-v));
    }
}

// ================= launcher =================
static inline int cdiv(long a, long b) { return (int)((a + b - 1) / b); }

extern "C" void kernel_launch(void* const* d_in, const int* in_sizes, int n_in,
                              void* d_out, int out_size)
{
    const float* x     = (const float*)d_in[0];
    const int*   ei    = (const int*)  d_in[1];
    const int*   batch = (const int*)  d_in[2];
    const float* W1    = (const float*)d_in[3];
    const float* as1   = (const float*)d_in[4];
    const float* ad1   = (const float*)d_in[5];
    const float* b1    = (const float*)d_in[6];
    const float* W2    = (const float*)d_in[7];
    const float* as2   = (const float*)d_in[8];
    const float* ad2   = (const float*)d_in[9];
    const float* b2    = (const float*)d_in[10];
    const float* W3    = (const float*)d_in[11];
    const float* as3   = (const float*)d_in[12];
    const float* ad3   = (const float*)d_in[13];
    const float* b3    = (const float*)d_in[14];

    __half *bufH, *bufH2, *xH;
    float *ssrc, *sdst, *ssrc2, *sdst2;
    cudaGetSymbolAddress((void**)&bufH,  g_bufH);
    cudaGetSymbolAddress((void**)&bufH2, g_bufH2);
    cudaGetSymbolAddress((void**)&xH,    g_xH);
    cudaGetSymbolAddress((void**)&ssrc,  g_ssrc);
    cudaGetSymbolAddress((void**)&sdst,  g_sdst);
    cudaGetSymbolAddress((void**)&ssrc2, g_ssrc2);
    cudaGetSymbolAddress((void**)&sdst2, g_sdst2);

    static cudaStream_t s2 = nullptr;
    static cudaEvent_t evFork = nullptr, evJoin = nullptr, evA = nullptr,
                       evG2 = nullptr, evB = nullptr, evG3 = nullptr;
    if (!s2) {
        cudaStreamCreateWithFlags(&s2, cudaStreamNonBlocking);
        cudaEventCreateWithFlags(&evFork, cudaEventDisableTiming);
        cudaEventCreateWithFlags(&evJoin, cudaEventDisableTiming);
        cudaEventCreateWithFlags(&evA, cudaEventDisableTiming);
        cudaEventCreateWithFlags(&evG2, cudaEventDisableTiming);
        cudaEventCreateWithFlags(&evB, cudaEventDisableTiming);
        cudaEventCreateWithFlags(&evG3, cudaEventDisableTiming);
    }

    const int T = 256;
    const int C0_GEMM = CHUNK / 64;                       // 782
    const int C1_GEMM = cdiv(N_NODES - CHUNK, 64);        // 781
    const int C0_AGG  = CHUNK / 8;                        // 6256
    const int C1_AGG  = cdiv(N_NODES - CHUNK, 8);         // 6244

    // ---------- fork: CSR build + pool_zero on side stream ----------
    cudaEventRecord(evFork, 0);
    cudaStreamWaitEvent(s2, evFork, 0);
    csr_zero_fill<<<cdiv(N_NODES, T), T, 0, s2>>>();
    csr_hist<<<cdiv(N_EDGES, T), T, 0, s2>>>(ei);
    csr_scan1<<<N_SCAN_BLKS, SCAN_BLK, 0, s2>>>();
    csr_scan2<<<1, 512, 0, s2>>>();
    csr_scan3<<<cdiv(N_NODES, T), T, 0, s2>>>();
    csr_scatter<<<cdiv(N_EDGES, T), T, 0, s2>>>(ei);
    pool_zero<<<3, T, 0, s2>>>();
    cudaEventRecord(evJoin, s2);

    // ---------- main: layer-1 GEMM (full range, overlaps CSR build) ----------
    gemm_wmma<128, 64, 4, 16, float><<<cdiv(N_NODES, 64), 128>>>(x, W1, as1, ad1, bufH, ssrc, sdst, 0);

    // ---------- join; pipelined layer1-agg -> layer2-gemm ----------
    cudaStreamWaitEvent(0, evJoin, 0);
    csr_aggN<4, 16><<<C0_AGG, T>>>(ssrc, sdst, bufH, b1, xH, 0, CHUNK);
    cudaEventRecord(evA, 0);
    cudaStreamWaitEvent(s2, evA, 0);
    gemm_wmma<64, 128, 4, 32, __half><<<C0_GEMM, 128, 0, s2>>>(xH, W2, as2, ad2, bufH2, ssrc2, sdst2, 0);
    cudaEventRecord(evG2, s2);
    csr_aggN<4, 16><<<C1_AGG, T>>>(ssrc, sdst, bufH, b1, xH, CHUNK, N_NODES);
    gemm_wmma<64, 128, 4, 32, __half><<<C1_GEMM, 128>>>(xH, W2, as2, ad2, bufH2, ssrc2, sdst2, CHUNK);
    cudaStreamWaitEvent(0, evG2, 0);

    // ---------- pipelined layer2-agg -> layer3-gemm ----------
    csr_aggN<4, 32><<<C0_AGG, T>>>(ssrc2, sdst2, bufH2, b2, xH, 0, CHUNK);
    cudaEventRecord(evB, 0);
    cudaStreamWaitEvent(s2, evB, 0);
    gemm_score_l3<<<C0_GEMM, 128, 0, s2>>>(xH, W3, as3, ad3, bufH, ssrc, sdst, 0);
    cudaEventRecord(evG3, s2);
    csr_aggN<4, 32><<<C1_AGG, T>>>(ssrc2, sdst2, bufH2, b2, xH, CHUNK, N_NODES);
    gemm_score_l3<<<C1_GEMM, 128>>>(xH, W3, as3, ad3, bufH, ssrc, sdst, CHUNK);
    cudaStreamWaitEvent(0, evG3, 0);

    // ---------- layer-3 aggregation fused with pooling ----------
    csr_agg_t8_pool<<<cdiv(N_NODES, T), T>>>(ssrc, sdst, bufH, b3, batch);
    pool_out<<<1, 512>>>((float*)d_out);
}

// round 15
// speedup vs baseline: 1.0077x; 1.0077x over previous
#include <cuda_runtime.h>
#include <cuda_fp16.h>
#include <mma.h>
#include <math.h>

#define N_NODES 100000
#define N_EDGES 1600000
#define N_GRAPHS 64
#define NEG_SLOPE 0.2f
#define SCAN_BLK 256
#define N_SCAN_BLKS ((N_NODES + SCAN_BLK - 1) / SCAN_BLK)   // 391

// ---------------- static scratch (no allocs allowed) ----------------
__device__ __half g_bufH[N_NODES * 128];  // h (fp16, gathered by aggregation)
__device__ __half g_xH  [N_NODES * 128];  // agg outputs (relu'd fp16, next GEMM's A)
__device__ float  g_ssrc[N_NODES * 4];
__device__ float  g_sdst[N_NODES * 4];
__device__ float  g_pool[N_GRAPHS * 8];
__device__ float  g_cnt [N_GRAPHS];
// CSR (dst-sorted incoming edges)
__device__ int g_rowptr[N_NODES + 1];
__device__ int g_fill  [N_NODES];
__device__ int g_srcsorted[N_EDGES];
__device__ int g_bsum[512];

__device__ __forceinline__ float lrelu(float x) { return x > 0.f ? x : NEG_SLOPE * x; }

__device__ __forceinline__ void ldh8f(const __half* p, float* o) {
    uint4 r = *reinterpret_cast<const uint4*>(p);
    float2 a = __half22float2(*reinterpret_cast<__half2*>(&r.x));
    float2 b = __half22float2(*reinterpret_cast<__half2*>(&r.y));
    float2 c = __half22float2(*reinterpret_cast<__half2*>(&r.z));
    float2 d = __half22float2(*reinterpret_cast<__half2*>(&r.w));
    o[0] = a.x; o[1] = a.y; o[2] = b.x; o[3] = b.y;
    o[4] = c.x; o[5] = c.y; o[6] = d.x; o[7] = d.y;
}

// ================= CSR build =================
__global__ void csr_zero_fill() {
    int i = blockIdx.x * blockDim.x + threadIdx.x;
    if (i < N_NODES) g_fill[i] = 0;
}

__global__ void csr_hist(const int* __restrict__ ei) {
    int e = blockIdx.x * blockDim.x + threadIdx.x;
    if (e < N_EDGES) atomicAdd(&g_fill[ei[N_EDGES + e]], 1);
}

__global__ void csr_scan1() {
    __shared__ int sh[SCAN_BLK];
    int t = threadIdx.x;
    int i = blockIdx.x * SCAN_BLK + t;
    int v = (i < N_NODES) ? g_fill[i] : 0;
    sh[t] = v;
    __syncthreads();
#pragma unroll
    for (int off = 1; off < SCAN_BLK; off <<= 1) {
        int add = (t >= off) ? sh[t - off] : 0;
        __syncthreads();
        sh[t] += add;
        __syncthreads();
    }
    if (i < N_NODES) g_rowptr[i] = sh[t] - v;
    if (t == SCAN_BLK - 1) g_bsum[blockIdx.x] = sh[t];
}

__global__ void csr_scan2() {
    __shared__ int sh[512];
    int t = threadIdx.x;
    int v = (t < N_SCAN_BLKS) ? g_bsum[t] : 0;
    sh[t] = v;
    __syncthreads();
#pragma unroll
    for (int off = 1; off < 512; off <<= 1) {
        int add = (t >= off) ? sh[t - off] : 0;
        __syncthreads();
        sh[t] += add;
        __syncthreads();
    }
    if (t < N_SCAN_BLKS) g_bsum[t] = sh[t] - v;
}

__global__ void csr_scan3() {
    int i = blockIdx.x * blockDim.x + threadIdx.x;
    if (i < N_NODES) {
        g_rowptr[i] += g_bsum[i >> 8];
        g_fill[i] = 0;
    }
    if (i == 0) g_rowptr[N_NODES] = N_EDGES;
}

__global__ void csr_scatter(const int* __restrict__ ei) {
    int e = blockIdx.x * blockDim.x + threadIdx.x;
    if (e >= N_EDGES) return;
    int d = ei[N_EDGES + e];
    int pos = g_rowptr[d] + atomicAdd(&g_fill[d], 1);
    g_srcsorted[pos] = ei[e];
}

// ================= WMMA GEMM + score epilogue =================
template<int K, int N, int H, int C, typename TIN>
__global__ void __launch_bounds__(128) gemm_wmma(
    const TIN* __restrict__ xin, const float* __restrict__ W,
    const float* __restrict__ asrc, const float* __restrict__ adst,
    __half* __restrict__ hout, float* __restrict__ ssrc, float* __restrict__ sdst)
{
    using namespace nvcuda;
    constexpr int KS  = K + 8;
    constexpr int NS  = N + 8;
    constexpr int NSF = N + 8;
    constexpr int NT  = N / 16;
    constexpr int KT  = K / 16;
    constexpr int ASZ = 64 * KS * 2;
    constexpr int BSZ = K * NS * 2;
    constexpr int CSZ = 64 * NSF * 4;
    constexpr int SMB = (ASZ + BSZ) > CSZ ? (ASZ + BSZ) : CSZ;
    __shared__ __align__(16) char smem[SMB];
    __half* As = reinterpret_cast<__half*>(smem);
    __half* Bs = reinterpret_cast<__half*>(smem + ASZ);
    float*  Cs = reinterpret_cast<float*>(smem);

    const int m0blk = blockIdx.x * 64;

    // ---- stage A ----
    {
        constexpr int CH = 64 * (K / 8);
        for (int c = threadIdx.x; c < CH; c += 128) {
            int rl = c / (K / 8);
            int kc = (c % (K / 8)) * 8;
            int row = min(m0blk + rl, N_NODES - 1);
            uint4 pk;
            if (sizeof(TIN) == 4) {
                const float4* p = reinterpret_cast<const float4*>((const float*)xin + (size_t)row * K + kc);
                float4 v0 = p[0], v1 = p[1];
                __half2 h0 = __floats2half2_rn(v0.x, v0.y);
                __half2 h1 = __floats2half2_rn(v0.z, v0.w);
                __half2 h2 = __floats2half2_rn(v1.x, v1.y);
                __half2 h3 = __floats2half2_rn(v1.z, v1.w);
                pk.x = *reinterpret_cast<unsigned*>(&h0);
                pk.y = *reinterpret_cast<unsigned*>(&h1);
                pk.z = *reinterpret_cast<unsigned*>(&h2);
                pk.w = *reinterpret_cast<unsigned*>(&h3);
            } else {
                pk = *reinterpret_cast<const uint4*>((const __half*)xin + (size_t)row * K + kc);
            }
            *reinterpret_cast<uint4*>(&As[rl * KS + kc]) = pk;
        }
    }
    // ---- stage B ----
    {
        constexpr int CH = K * (N / 8);
        for (int c = threadIdx.x; c < CH; c += 128) {
            int k  = c / (N / 8);
            int nc = (c % (N / 8)) * 8;
            const float4* p = reinterpret_cast<const float4*>(W + (size_t)k * N + nc);
            float4 v0 = p[0], v1 = p[1];
            __half2 h0 = __floats2half2_rn(v0.x, v0.y);
            __half2 h1 = __floats2half2_rn(v0.z, v0.w);
            __half2 h2 = __floats2half2_rn(v1.x, v1.y);
            __half2 h3 = __floats2half2_rn(v1.z, v1.w);
            uint4 pk;
            pk.x = *reinterpret_cast<unsigned*>(&h0);
            pk.y = *reinterpret_cast<unsigned*>(&h1);
            pk.z = *reinterpret_cast<unsigned*>(&h2);
            pk.w = *reinterpret_cast<unsigned*>(&h3);
            *reinterpret_cast<uint4*>(&Bs[k * NS + nc]) = pk;
        }
    }
    __syncthreads();

    const int warp = threadIdx.x >> 5;

    wmma::fragment<wmma::accumulator, 16, 16, 16, float> acc[NT];
#pragma unroll
    for (int nt = 0; nt < NT; nt++) wmma::fill_fragment(acc[nt], 0.f);

#pragma unroll
    for (int kt = 0; kt < KT; kt++) {
        wmma::fragment<wmma::matrix_a, 16, 16, 16, __half, wmma::row_major> af;
        wmma::load_matrix_sync(af, As + (warp * 16) * KS + kt * 16, KS);
#pragma unroll
        for (int nt = 0; nt < NT; nt++) {
            wmma::fragment<wmma::matrix_b, 16, 16, 16, __half, wmma::row_major> bf;
            wmma::load_matrix_sync(bf, Bs + (kt * 16) * NS + nt * 16, NS);
            wmma::mma_sync(acc[nt], af, bf, acc[nt]);
        }
    }

    __syncthreads();
#pragma unroll
    for (int nt = 0; nt < NT; nt++)
        wmma::store_matrix_sync(Cs + (warp * 16) * NSF + nt * 16, acc[nt], NSF, wmma::mem_row_major);
    __syncthreads();

    // ---- epilogue: 2 threads per row, each owns N/2 cols = whole heads ----
    {
        constexpr int HALF = N / 2;
        constexpr int HH   = (H >= 2) ? H / 2 : 1;
        const int row  = threadIdx.x & 63;
        const int half = threadIdx.x >> 6;
        const int n    = m0blk + row;
        if (n < N_NODES) {
            const int c0 = half * HALF;
            const float* cr = Cs + row * NSF + c0;
            float sc[HH], dc[HH];
#pragma unroll
            for (int hh = 0; hh < HH; hh++) { sc[hh] = 0.f; dc[hh] = 0.f; }
#pragma unroll
            for (int i = 0; i < HALF; i += 8) {
                float4 v0 = *reinterpret_cast<const float4*>(cr + i);
                float4 v1 = *reinterpret_cast<const float4*>(cr + i + 4);
                int hh = i / C;
                sc[hh] += v0.x * asrc[c0 + i + 0] + v0.y * asrc[c0 + i + 1]
                        + v0.z * asrc[c0 + i + 2] + v0.w * asrc[c0 + i + 3]
                        + v1.x * asrc[c0 + i + 4] + v1.y * asrc[c0 + i + 5]
                        + v1.z * asrc[c0 + i + 6] + v1.w * asrc[c0 + i + 7];
                dc[hh] += v0.x * adst[c0 + i + 0] + v0.y * adst[c0 + i + 1]
                        + v0.z * adst[c0 + i + 2] + v0.w * adst[c0 + i + 3]
                        + v1.x * adst[c0 + i + 4] + v1.y * adst[c0 + i + 5]
                        + v1.z * adst[c0 + i + 6] + v1.w * adst[c0 + i + 7];
                __half2 p0 = __floats2half2_rn(v0.x, v0.y);
                __half2 p1 = __floats2half2_rn(v0.z, v0.w);
                __half2 p2 = __floats2half2_rn(v1.x, v1.y);
                __half2 p3 = __floats2half2_rn(v1.z, v1.w);
                uint4 pk;
                pk.x = *reinterpret_cast<unsigned*>(&p0);
                pk.y = *reinterpret_cast<unsigned*>(&p1);
                pk.z = *reinterpret_cast<unsigned*>(&p2);
                pk.w = *reinterpret_cast<unsigned*>(&p3);
                *reinterpret_cast<uint4*>(&hout[(size_t)n * N + c0 + i]) = pk;
            }
            const int hb = half * HH;
#pragma unroll
            for (int hh = 0; hh < HH; hh++) {
                ssrc[n * H + hb + hh] = sc[hh];
                sdst[n * H + hb + hh] = dc[hh];
            }
        }
    }
}

// ================= layer-3 GEMM (HC=8, scalar, fp16 input) =================
__global__ void gemm_score_l3(const __half* __restrict__ x, const float* __restrict__ W,
                              const float* __restrict__ asrc, const float* __restrict__ adst,
                              __half* __restrict__ hout, float* __restrict__ ssrc,
                              float* __restrict__ sdst)
{
    constexpr int K = 128, HC = 8, TPN = 2, NB = 64, TPB = 128;
    __shared__ float xs[NB * K];

    const int base = blockIdx.x * NB;
    for (int i = threadIdx.x; i < NB * K; i += TPB) {
        int n = base + i / K;
        xs[i] = (n < N_NODES) ? __half2float(x[(size_t)n * K + (i % K)]) : 0.f;
    }
    __syncthreads();

    const int local = threadIdx.x / TPN;
    const int tj    = threadIdx.x % TPN;
    const int j0    = tj * 4;
    const int n     = base + local;
    if (n >= N_NODES) return;

    const float* xr = &xs[local * K];
    const float4* W4 = reinterpret_cast<const float4*>(W);
    float a0 = 0.f, a1 = 0.f, a2 = 0.f, a3 = 0.f;
#pragma unroll 8
    for (int k = 0; k < K; k++) {
        float xv = xr[k];
        float4 wv = W4[k * TPN + tj];
        a0 = fmaf(xv, wv.x, a0);
        a1 = fmaf(xv, wv.y, a1);
        a2 = fmaf(xv, wv.z, a2);
        a3 = fmaf(xv, wv.w, a3);
    }

    {
        __half2 lo = __floats2half2_rn(a0, a1);
        __half2 hi = __floats2half2_rn(a2, a3);
        uint2 pk;
        pk.x = *reinterpret_cast<unsigned*>(&lo);
        pk.y = *reinterpret_cast<unsigned*>(&hi);
        *reinterpret_cast<uint2*>(&hout[(size_t)n * HC + j0]) = pk;
    }

    float vs = a0 * asrc[j0] + a1 * asrc[j0 + 1] + a2 * asrc[j0 + 2] + a3 * asrc[j0 + 3];
    float vd = a0 * adst[j0] + a1 * adst[j0 + 1] + a2 * adst[j0 + 2] + a3 * adst[j0 + 3];
    vs += __shfl_down_sync(0xffffffffu, vs, 1);
    vd += __shfl_down_sync(0xffffffffu, vd, 1);
    if (tj == 0) {
        ssrc[n] = vs;
        sdst[n] = vd;
    }
}

// ================= CSR aggregation: warp per node, 4-deep MLP =================
template<int H, int C>
__global__ void csr_aggN(const float* __restrict__ ssrc, const float* __restrict__ sdst,
                         const __half* __restrict__ hbuf, const float* __restrict__ bias,
                         __half* __restrict__ out)
{
    constexpr int HC   = H * C;           // 64 or 128
    constexpr int LPE  = HC / 8;          // lanes per edge: 8 or 16
    constexpr int NSUB = 32 / LPE;        // 4 or 2
    int n = blockIdx.x * (blockDim.x / 32) + (threadIdx.x >> 5);
    if (n >= N_NODES) return;
    int lane = threadIdx.x & 31;
    int sub  = lane / LPE;
    int cpos = lane % LPE;
    int j0   = cpos * 8;
    int h    = j0 / C;

    const float sds = sdst[n * H + h];
    float acc[8];
#pragma unroll
    for (int v = 0; v < 8; v++) acc[v] = 0.f;
    float den = 0.f;
    if (sub == 0) {
        float wself = __expf(lrelu(ssrc[n * H + h] + sds));
        den = wself;
        float hv[8];
        ldh8f(&hbuf[(size_t)n * HC + j0], hv);
#pragma unroll
        for (int v = 0; v < 8; v++) acc[v] = wself * hv[v];
    }

    int e   = g_rowptr[n];
    int end = g_rowptr[n + 1];
    // 4-deep main loop: 4 independent gathers in flight per lane
    for (; e + 4 * NSUB - 1 < end; e += 4 * NSUB) {
        int sA = g_srcsorted[e + sub];
        int sB = g_srcsorted[e + NSUB + sub];
        int sC = g_srcsorted[e + 2 * NSUB + sub];
        int sD = g_srcsorted[e + 3 * NSUB + sub];
        float wA = __expf(lrelu(ssrc[sA * H + h] + sds));
        float wB = __expf(lrelu(ssrc[sB * H + h] + sds));
        float wC = __expf(lrelu(ssrc[sC * H + h] + sds));
        float wD = __expf(lrelu(ssrc[sD * H + h] + sds));
        float hA[8], hB[8], hC[8], hD[8];
        ldh8f(&hbuf[(size_t)sA * HC + j0], hA);
        ldh8f(&hbuf[(size_t)sB * HC + j0], hB);
        ldh8f(&hbuf[(size_t)sC * HC + j0], hC);
        ldh8f(&hbuf[(size_t)sD * HC + j0], hD);
#pragma unroll
        for (int v = 0; v < 8; v++)
            acc[v] += (wA * hA[v] + wB * hB[v]) + (wC * hC[v] + wD * hD[v]);
        den += (wA + wB) + (wC + wD);
    }
    // 2-deep
    for (; e + 2 * NSUB - 1 < end; e += 2 * NSUB) {
        int sA = g_srcsorted[e + sub];
        int sB = g_srcsorted[e + NSUB + sub];
        float wA = __expf(lrelu(ssrc[sA * H + h] + sds));
        float wB = __expf(lrelu(ssrc[sB * H + h] + sds));
        float hA[8], hB[8];
        ldh8f(&hbuf[(size_t)sA * HC + j0], hA);
        ldh8f(&hbuf[(size_t)sB * HC + j0], hB);
#pragma unroll
        for (int v = 0; v < 8; v++) acc[v] += wA * hA[v] + wB * hB[v];
        den += wA + wB;
    }
    // predicated tail
    for (; e < end; e += NSUB) {
        int idx    = e + sub;
        bool valid = idx < end;
        int s = g_srcsorted[valid ? idx : e];
        float w = valid ? __expf(lrelu(ssrc[s * H + h] + sds)) : 0.f;
        float hv[8];
        ldh8f(&hbuf[(size_t)s * HC + j0], hv);
#pragma unroll
        for (int v = 0; v < 8; v++) acc[v] += w * hv[v];
        den += w;
    }

#pragma unroll
    for (int off = LPE; off < 32; off <<= 1) {
#pragma unroll
        for (int v = 0; v < 8; v++) acc[v] += __shfl_xor_sync(0xffffffffu, acc[v], off);
        den += __shfl_xor_sync(0xffffffffu, den, off);
    }

    if (sub == 0) {
        float inv = 1.f / den;
        float r[8];
#pragma unroll
        for (int v = 0; v < 8; v++) r[v] = fmaxf(acc[v] * inv + bias[j0 + v], 0.f);
        __half2 p0 = __floats2half2_rn(r[0], r[1]);
        __half2 p1 = __floats2half2_rn(r[2], r[3]);
        __half2 p2 = __floats2half2_rn(r[4], r[5]);
        __half2 p3 = __floats2half2_rn(r[6], r[7]);
        uint4 pk;
        pk.x = *reinterpret_cast<unsigned*>(&p0);
        pk.y = *reinterpret_cast<unsigned*>(&p1);
        pk.z = *reinterpret_cast<unsigned*>(&p2);
        pk.w = *reinterpret_cast<unsigned*>(&p3);
        *reinterpret_cast<uint4*>(&out[(size_t)n * HC + j0]) = pk;
    }
}

// ================= Layer 3: thread-per-node (HC=8), fused into pooling =================
__global__ void csr_agg_t8_pool(const float* __restrict__ ssrc, const float* __restrict__ sdst,
                                const __half* __restrict__ hbuf, const float* __restrict__ bias,
                                const int* __restrict__ batch)
{
    int n = blockIdx.x * blockDim.x + threadIdx.x;
    if (n >= N_NODES) return;
    const float sds   = sdst[n];
    const float wself = __expf(lrelu(ssrc[n] + sds));

    float a[8], hv[8];
    ldh8f(&hbuf[(size_t)n * 8], hv);
#pragma unroll
    for (int v = 0; v < 8; v++) a[v] = wself * hv[v];
    float den = wself;

    int e = g_rowptr[n], end = g_rowptr[n + 1];
    for (; e + 3 < end; e += 4) {
        int s0 = g_srcsorted[e],     s1 = g_srcsorted[e + 1];
        int s2 = g_srcsorted[e + 2], s3 = g_srcsorted[e + 3];
        float w0 = __expf(lrelu(ssrc[s0] + sds));
        float w1 = __expf(lrelu(ssrc[s1] + sds));
        float w2 = __expf(lrelu(ssrc[s2] + sds));
        float w3 = __expf(lrelu(ssrc[s3] + sds));
        float h0[8], h1[8], h2[8], h3[8];
        ldh8f(&hbuf[(size_t)s0 * 8], h0);
        ldh8f(&hbuf[(size_t)s1 * 8], h1);
        ldh8f(&hbuf[(size_t)s2 * 8], h2);
        ldh8f(&hbuf[(size_t)s3 * 8], h3);
#pragma unroll
        for (int v = 0; v < 8; v++)
            a[v] += (w0 * h0[v] + w1 * h1[v]) + (w2 * h2[v] + w3 * h3[v]);
        den += (w0 + w1) + (w2 + w3);
    }
    for (; e < end; e++) {
        int s = g_srcsorted[e];
        float w = __expf(lrelu(ssrc[s] + sds));
        ldh8f(&hbuf[(size_t)s * 8], hv);
#pragma unroll
        for (int v = 0; v < 8; v++) a[v] += w * hv[v];
        den += w;
    }
    float inv = 1.f / den;
    int g = batch[n];
    float* pp = &g_pool[g * 8];
#pragma unroll
    for (int v = 0; v < 8; v++) atomicAdd(pp + v, a[v] * inv + bias[v]);
    atomicAdd(&g_cnt[g], 1.f);
}

// ================= pooling epilogue =================
__global__ void pool_zero() {
    int i = blockIdx.x * blockDim.x + threadIdx.x;
    if (i < N_GRAPHS * 8) g_pool[i] = 0.f;
    if (i < N_GRAPHS)     g_cnt[i]  = 0.f;
}

__global__ void pool_out(float* __restrict__ out)
{
    int i = threadIdx.x;
    if (i < N_GRAPHS * 8) {
        float v = g_pool[i] / fmaxf(g_cnt[i / 8], 1.f);
        out[i] = 1.f / (1.f + expf(-v));
    }
}

// ================= launcher (round-12 serial structure) =================
static inline int cdiv(long a, long b) { return (int)((a + b - 1) / b); }

extern "C" void kernel_launch(void* const* d_in, const int* in_sizes, int n_in,
                              void* d_out, int out_size)
{
    const float* x     = (const float*)d_in[0];
    const int*   ei    = (const int*)  d_in[1];
    const int*   batch = (const int*)  d_in[2];
    const float* W1    = (const float*)d_in[3];
    const float* as1   = (const float*)d_in[4];
    const float* ad1   = (const float*)d_in[5];
    const float* b1    = (const float*)d_in[6];
    const float* W2    = (const float*)d_in[7];
    const float* as2   = (const float*)d_in[8];
    const float* ad2   = (const float*)d_in[9];
    const float* b2    = (const float*)d_in[10];
    const float* W3    = (const float*)d_in[11];
    const float* as3   = (const float*)d_in[12];
    const float* ad3   = (const float*)d_in[13];
    const float* b3    = (const float*)d_in[14];

    __half *bufH, *xH;
    float *ssrc, *sdst;
    cudaGetSymbolAddress((void**)&bufH, g_bufH);
    cudaGetSymbolAddress((void**)&xH,   g_xH);
    cudaGetSymbolAddress((void**)&ssrc, g_ssrc);
    cudaGetSymbolAddress((void**)&sdst, g_sdst);

    static cudaStream_t s2 = nullptr;
    static cudaEvent_t evFork = nullptr, evJoin = nullptr;
    if (!s2) {
        cudaStreamCreateWithFlags(&s2, cudaStreamNonBlocking);
        cudaEventCreateWithFlags(&evFork, cudaEventDisableTiming);
        cudaEventCreateWithFlags(&evJoin, cudaEventDisableTiming);
    }

    const int T = 256;
    const int GEMM_BLKS = cdiv(N_NODES, 64);   // 1563

    // ---------- fork: CSR build + pool_zero on side stream ----------
    cudaEventRecord(evFork, 0);
    cudaStreamWaitEvent(s2, evFork, 0);
    csr_zero_fill<<<cdiv(N_NODES, T), T, 0, s2>>>();
    csr_hist<<<cdiv(N_EDGES, T), T, 0, s2>>>(ei);
    csr_scan1<<<N_SCAN_BLKS, SCAN_BLK, 0, s2>>>();
    csr_scan2<<<1, 512, 0, s2>>>();
    csr_scan3<<<cdiv(N_NODES, T), T, 0, s2>>>();
    csr_scatter<<<cdiv(N_EDGES, T), T, 0, s2>>>(ei);
    pool_zero<<<3, T, 0, s2>>>();
    cudaEventRecord(evJoin, s2);

    // ---------- main stream: layer-1 GEMM (overlaps CSR build) ----------
    gemm_wmma<128, 64, 4, 16, float><<<GEMM_BLKS, 128>>>(x, W1, as1, ad1, bufH, ssrc, sdst);

    // ---------- join, then serial layers ----------
    cudaStreamWaitEvent(0, evJoin, 0);
    csr_aggN<4, 16><<<cdiv(N_NODES, 8), T>>>(ssrc, sdst, bufH, b1, xH);

    gemm_wmma<64, 128, 4, 32, __half><<<GEMM_BLKS, 128>>>(xH, W2, as2, ad2, bufH, ssrc, sdst);
    csr_aggN<4, 32><<<cdiv(N_NODES, 8), T>>>(ssrc, sdst, bufH, b2, xH);

    gemm_score_l3<<<cdiv(N_NODES, 64), 128>>>(xH, W3, as3, ad3, bufH, ssrc, sdst);
    csr_agg_t8_pool<<<cdiv(N_NODES, T), T>>>(ssrc, sdst, bufH, b3, batch);
    pool_out<<<1, 512>>>((float*)d_out);
}

// round 16
// speedup vs baseline: 1.0444x; 1.0364x over previous
#include <cuda_runtime.h>
#include <cuda_fp16.h>
#include <mma.h>
#include <math.h>

#define N_NODES 100000
#define N_EDGES 1600000
#define N_GRAPHS 64
#define NEG_SLOPE 0.2f
#define SCAN_BLK 256
#define N_SCAN_BLKS ((N_NODES + SCAN_BLK - 1) / SCAN_BLK)   // 391

// ---------------- static scratch (no allocs allowed) ----------------
__device__ __half g_bufH [N_NODES * 128];  // layer-1 h / layer-3 h (fp16)
__device__ __half g_bufH2[N_NODES * 128];  // layer-2 h (fp16)
__device__ float  g_ssrc [N_NODES * 4];    // layer-1/3 scores
__device__ float  g_sdst [N_NODES * 4];
__device__ float  g_ssrc2[N_NODES * 4];    // layer-2 scores
__device__ float  g_sdst2[N_NODES * 4];
__device__ float  g_pool[N_GRAPHS * 8];
__device__ float  g_cnt [N_GRAPHS];
// CSR (dst-sorted incoming edges)
__device__ int g_rowptr[N_NODES + 1];
__device__ int g_fill  [N_NODES];
__device__ int g_srcsorted[N_EDGES];
__device__ int g_bsum[512];

__device__ __forceinline__ float lrelu(float x) { return x > 0.f ? x : NEG_SLOPE * x; }

__device__ __forceinline__ void ldh8f(const __half* p, float* o) {
    uint4 r = *reinterpret_cast<const uint4*>(p);
    float2 a = __half22float2(*reinterpret_cast<__half2*>(&r.x));
    float2 b = __half22float2(*reinterpret_cast<__half2*>(&r.y));
    float2 c = __half22float2(*reinterpret_cast<__half2*>(&r.z));
    float2 d = __half22float2(*reinterpret_cast<__half2*>(&r.w));
    o[0] = a.x; o[1] = a.y; o[2] = b.x; o[3] = b.y;
    o[4] = c.x; o[5] = c.y; o[6] = d.x; o[7] = d.y;
}

// ================= CSR build =================
__global__ void csr_zero_fill() {
    int i = blockIdx.x * blockDim.x + threadIdx.x;
    if (i < N_NODES) g_fill[i] = 0;
}

__global__ void csr_hist(const int* __restrict__ ei) {
    int e = blockIdx.x * blockDim.x + threadIdx.x;
    if (e < N_EDGES) atomicAdd(&g_fill[ei[N_EDGES + e]], 1);
}

__global__ void csr_scan1() {
    __shared__ int sh[SCAN_BLK];
    int t = threadIdx.x;
    int i = blockIdx.x * SCAN_BLK + t;
    int v = (i < N_NODES) ? g_fill[i] : 0;
    sh[t] = v;
    __syncthreads();
#pragma unroll
    for (int off = 1; off < SCAN_BLK; off <<= 1) {
        int add = (t >= off) ? sh[t - off] : 0;
        __syncthreads();
        sh[t] += add;
        __syncthreads();
    }
    if (i < N_NODES) g_rowptr[i] = sh[t] - v;
    if (t == SCAN_BLK - 1) g_bsum[blockIdx.x] = sh[t];
}

__global__ void csr_scan2() {
    __shared__ int sh[512];
    int t = threadIdx.x;
    int v = (t < N_SCAN_BLKS) ? g_bsum[t] : 0;
    sh[t] = v;
    __syncthreads();
#pragma unroll
    for (int off = 1; off < 512; off <<= 1) {
        int add = (t >= off) ? sh[t - off] : 0;
        __syncthreads();
        sh[t] += add;
        __syncthreads();
    }
    if (t < N_SCAN_BLKS) g_bsum[t] = sh[t] - v;
}

__global__ void csr_scan3() {
    int i = blockIdx.x * blockDim.x + threadIdx.x;
    if (i < N_NODES) {
        g_rowptr[i] += g_bsum[i >> 8];
        g_fill[i] = 0;
    }
    if (i == 0) g_rowptr[N_NODES] = N_EDGES;
}

__global__ void csr_scatter(const int* __restrict__ ei) {
    int e = blockIdx.x * blockDim.x + threadIdx.x;
    if (e >= N_EDGES) return;
    int d = ei[N_EDGES + e];
    int pos = g_rowptr[d] + atomicAdd(&g_fill[d], 1);
    g_srcsorted[pos] = ei[e];
}

// ================= WMMA GEMM + score epilogue (layer 1) =================
template<int K, int N, int H, int C, typename TIN>
__global__ void __launch_bounds__(128) gemm_wmma(
    const TIN* __restrict__ xin, const float* __restrict__ W,
    const float* __restrict__ asrc, const float* __restrict__ adst,
    __half* __restrict__ hout, float* __restrict__ ssrc, float* __restrict__ sdst)
{
    using namespace nvcuda;
    constexpr int KS  = K + 8;
    constexpr int NS  = N + 8;
    constexpr int NSF = N + 8;
    constexpr int NT  = N / 16;
    constexpr int KT  = K / 16;
    constexpr int ASZ = 64 * KS * 2;
    constexpr int BSZ = K * NS * 2;
    constexpr int CSZ = 64 * NSF * 4;
    constexpr int SMB = (ASZ + BSZ) > CSZ ? (ASZ + BSZ) : CSZ;
    __shared__ __align__(16) char smem[SMB];
    __half* As = reinterpret_cast<__half*>(smem);
    __half* Bs = reinterpret_cast<__half*>(smem + ASZ);
    float*  Cs = reinterpret_cast<float*>(smem);

    const int m0blk = blockIdx.x * 64;

    {
        constexpr int CH = 64 * (K / 8);
        for (int c = threadIdx.x; c < CH; c += 128) {
            int rl = c / (K / 8);
            int kc = (c % (K / 8)) * 8;
            int row = min(m0blk + rl, N_NODES - 1);
            uint4 pk;
            if (sizeof(TIN) == 4) {
                const float4* p = reinterpret_cast<const float4*>((const float*)xin + (size_t)row * K + kc);
                float4 v0 = p[0], v1 = p[1];
                __half2 h0 = __floats2half2_rn(v0.x, v0.y);
                __half2 h1 = __floats2half2_rn(v0.z, v0.w);
                __half2 h2 = __floats2half2_rn(v1.x, v1.y);
                __half2 h3 = __floats2half2_rn(v1.z, v1.w);
                pk.x = *reinterpret_cast<unsigned*>(&h0);
                pk.y = *reinterpret_cast<unsigned*>(&h1);
                pk.z = *reinterpret_cast<unsigned*>(&h2);
                pk.w = *reinterpret_cast<unsigned*>(&h3);
            } else {
                pk = *reinterpret_cast<const uint4*>((const __half*)xin + (size_t)row * K + kc);
            }
            *reinterpret_cast<uint4*>(&As[rl * KS + kc]) = pk;
        }
    }
    {
        constexpr int CH = K * (N / 8);
        for (int c = threadIdx.x; c < CH; c += 128) {
            int k  = c / (N / 8);
            int nc = (c % (N / 8)) * 8;
            const float4* p = reinterpret_cast<const float4*>(W + (size_t)k * N + nc);
            float4 v0 = p[0], v1 = p[1];
            __half2 h0 = __floats2half2_rn(v0.x, v0.y);
            __half2 h1 = __floats2half2_rn(v0.z, v0.w);
            __half2 h2 = __floats2half2_rn(v1.x, v1.y);
            __half2 h3 = __floats2half2_rn(v1.z, v1.w);
            uint4 pk;
            pk.x = *reinterpret_cast<unsigned*>(&h0);
            pk.y = *reinterpret_cast<unsigned*>(&h1);
            pk.z = *reinterpret_cast<unsigned*>(&h2);
            pk.w = *reinterpret_cast<unsigned*>(&h3);
            *reinterpret_cast<uint4*>(&Bs[k * NS + nc]) = pk;
        }
    }
    __syncthreads();

    const int warp = threadIdx.x >> 5;

    wmma::fragment<wmma::accumulator, 16, 16, 16, float> acc[NT];
#pragma unroll
    for (int nt = 0; nt < NT; nt++) wmma::fill_fragment(acc[nt], 0.f);

#pragma unroll
    for (int kt = 0; kt < KT; kt++) {
        wmma::fragment<wmma::matrix_a, 16, 16, 16, __half, wmma::row_major> af;
        wmma::load_matrix_sync(af, As + (warp * 16) * KS + kt * 16, KS);
#pragma unroll
        for (int nt = 0; nt < NT; nt++) {
            wmma::fragment<wmma::matrix_b, 16, 16, 16, __half, wmma::row_major> bf;
            wmma::load_matrix_sync(bf, Bs + (kt * 16) * NS + nt * 16, NS);
            wmma::mma_sync(acc[nt], af, bf, acc[nt]);
        }
    }

    __syncthreads();
#pragma unroll
    for (int nt = 0; nt < NT; nt++)
        wmma::store_matrix_sync(Cs + (warp * 16) * NSF + nt * 16, acc[nt], NSF, wmma::mem_row_major);
    __syncthreads();

    {
        constexpr int HALF = N / 2;
        constexpr int HH   = (H >= 2) ? H / 2 : 1;
        const int row  = threadIdx.x & 63;
        const int half = threadIdx.x >> 6;
        const int n    = m0blk + row;
        if (n < N_NODES) {
            const int c0 = half * HALF;
            const float* cr = Cs + row * NSF + c0;
            float sc[HH], dc[HH];
#pragma unroll
            for (int hh = 0; hh < HH; hh++) { sc[hh] = 0.f; dc[hh] = 0.f; }
#pragma unroll
            for (int i = 0; i < HALF; i += 8) {
                float4 v0 = *reinterpret_cast<const float4*>(cr + i);
                float4 v1 = *reinterpret_cast<const float4*>(cr + i + 4);
                int hh = i / C;
                sc[hh] += v0.x * asrc[c0 + i + 0] + v0.y * asrc[c0 + i + 1]
                        + v0.z * asrc[c0 + i + 2] + v0.w * asrc[c0 + i + 3]
                        + v1.x * asrc[c0 + i + 4] + v1.y * asrc[c0 + i + 5]
                        + v1.z * asrc[c0 + i + 6] + v1.w * asrc[c0 + i + 7];
                dc[hh] += v0.x * adst[c0 + i + 0] + v0.y * adst[c0 + i + 1]
                        + v0.z * adst[c0 + i + 2] + v0.w * adst[c0 + i + 3]
                        + v1.x * adst[c0 + i + 4] + v1.y * adst[c0 + i + 5]
                        + v1.z * adst[c0 + i + 6] + v1.w * adst[c0 + i + 7];
                __half2 p0 = __floats2half2_rn(v0.x, v0.y);
                __half2 p1 = __floats2half2_rn(v0.z, v0.w);
                __half2 p2 = __floats2half2_rn(v1.x, v1.y);
                __half2 p3 = __floats2half2_rn(v1.z, v1.w);
                uint4 pk;
                pk.x = *reinterpret_cast<unsigned*>(&p0);
                pk.y = *reinterpret_cast<unsigned*>(&p1);
                pk.z = *reinterpret_cast<unsigned*>(&p2);
                pk.w = *reinterpret_cast<unsigned*>(&p3);
                *reinterpret_cast<uint4*>(&hout[(size_t)n * N + c0 + i]) = pk;
            }
            const int hb = half * HH;
#pragma unroll
            for (int hh = 0; hh < HH; hh++) {
                ssrc[n * H + hb + hh] = sc[hh];
                sdst[n * H + hb + hh] = dc[hh];
            }
        }
    }
}

// ================= FUSED: layer-1 agg (HC=64) + layer-2 wmma GEMM =================
// 256 threads. Phase 1: 8 warps x 8 nodes, MLP-2 agg (round-12 loop), relu'd fp16
// A-tile straight into smem. Phase 2: wmma K=64,N=128 + score epilogue.
__global__ void __launch_bounds__(256) fused_agg1_gemm2(
    const float* __restrict__ ssrc, const float* __restrict__ sdst,
    const __half* __restrict__ hbuf, const float* __restrict__ b1,
    const float* __restrict__ W2, const float* __restrict__ as2,
    const float* __restrict__ ad2,
    __half* __restrict__ hout2, float* __restrict__ ssrc2, float* __restrict__ sdst2)
{
    using namespace nvcuda;
    constexpr int KS2 = 72;      // A stride (halves), K=64
    constexpr int NS2 = 136;     // B stride (halves), N=128
    constexpr int NSF = 136;     // C stride (floats)
    constexpr int ASZ = 64 * KS2 * 2;   // 9216
    constexpr int CSZ = 64 * NSF * 4;   // 34816 (> ASZ+BSZ=26624)
    __shared__ __align__(16) char smem[CSZ];
    __half* As = reinterpret_cast<__half*>(smem);
    __half* Bs = reinterpret_cast<__half*>(smem + ASZ);
    float*  Cs = reinterpret_cast<float*>(smem);

    const int blk64 = blockIdx.x * 64;
    const int wid  = threadIdx.x >> 5;
    const int lane = threadIdx.x & 31;

    // ---- stage B: W2 (64 x 128 fp32 -> fp16) ----
    for (int c = threadIdx.x; c < 64 * 16; c += 256) {
        int k  = c >> 4;
        int nc = (c & 15) * 8;
        const float4* p = reinterpret_cast<const float4*>(W2 + (size_t)k * 128 + nc);
        float4 v0 = p[0], v1 = p[1];
        __half2 h0 = __floats2half2_rn(v0.x, v0.y);
        __half2 h1 = __floats2half2_rn(v0.z, v0.w);
        __half2 h2 = __floats2half2_rn(v1.x, v1.y);
        __half2 h3 = __floats2half2_rn(v1.z, v1.w);
        uint4 pk;
        pk.x = *reinterpret_cast<unsigned*>(&h0);
        pk.y = *reinterpret_cast<unsigned*>(&h1);
        pk.z = *reinterpret_cast<unsigned*>(&h2);
        pk.w = *reinterpret_cast<unsigned*>(&h3);
        *reinterpret_cast<uint4*>(&Bs[k * NS2 + nc]) = pk;
    }

    // ---- phase 1: agg 8 nodes per warp (H=4, C=16, LPE=8, NSUB=4) ----
    {
        const int sub  = lane >> 3;        // 0..3
        const int cpos = lane & 7;         // 0..7
        const int j0   = cpos * 8;
        const int h    = j0 / 16;          // head
        for (int r = 0; r < 8; r++) {
            const int lrow = wid * 8 + r;
            const int n    = blk64 + lrow;
            if (n >= N_NODES) break;       // warp-uniform

            const float sds = sdst[n * 4 + h];
            float acc[8];
#pragma unroll
            for (int v = 0; v < 8; v++) acc[v] = 0.f;
            float den = 0.f;
            if (sub == 0) {
                float wself = __expf(lrelu(ssrc[n * 4 + h] + sds));
                den = wself;
                float hv[8];
                ldh8f(&hbuf[(size_t)n * 64 + j0], hv);
#pragma unroll
                for (int v = 0; v < 8; v++) acc[v] = wself * hv[v];
            }

            int e   = g_rowptr[n];
            int end = g_rowptr[n + 1];
            for (; e + 7 < end; e += 8) {
                int sA = g_srcsorted[e + sub];
                int sB = g_srcsorted[e + 4 + sub];
                float wA = __expf(lrelu(ssrc[sA * 4 + h] + sds));
                float wB = __expf(lrelu(ssrc[sB * 4 + h] + sds));
                float hA[8], hB[8];
                ldh8f(&hbuf[(size_t)sA * 64 + j0], hA);
                ldh8f(&hbuf[(size_t)sB * 64 + j0], hB);
#pragma unroll
                for (int v = 0; v < 8; v++) acc[v] += wA * hA[v] + wB * hB[v];
                den += wA + wB;
            }
            for (; e < end; e += 4) {
                int idx    = e + sub;
                bool valid = idx < end;
                int s = g_srcsorted[valid ? idx : e];
                float w = valid ? __expf(lrelu(ssrc[s * 4 + h] + sds)) : 0.f;
                float hv[8];
                ldh8f(&hbuf[(size_t)s * 64 + j0], hv);
#pragma unroll
                for (int v = 0; v < 8; v++) acc[v] += w * hv[v];
                den += w;
            }

#pragma unroll
            for (int off = 8; off < 32; off <<= 1) {
#pragma unroll
                for (int v = 0; v < 8; v++) acc[v] += __shfl_xor_sync(0xffffffffu, acc[v], off);
                den += __shfl_xor_sync(0xffffffffu, den, off);
            }

            if (sub == 0) {
                float inv = 1.f / den;
                float rr[8];
#pragma unroll
                for (int v = 0; v < 8; v++) rr[v] = fmaxf(acc[v] * inv + b1[j0 + v], 0.f);
                __half2 p0 = __floats2half2_rn(rr[0], rr[1]);
                __half2 p1 = __floats2half2_rn(rr[2], rr[3]);
                __half2 p2 = __floats2half2_rn(rr[4], rr[5]);
                __half2 p3 = __floats2half2_rn(rr[6], rr[7]);
                uint4 pk;
                pk.x = *reinterpret_cast<unsigned*>(&p0);
                pk.y = *reinterpret_cast<unsigned*>(&p1);
                pk.z = *reinterpret_cast<unsigned*>(&p2);
                pk.w = *reinterpret_cast<unsigned*>(&p3);
                *reinterpret_cast<uint4*>(&As[lrow * KS2 + j0]) = pk;
            }
        }
    }
    __syncthreads();

    // ---- phase 2: wmma (K=64, N=128). 8 warps: rows (wid&3)*16, n-half (wid>>2) ----
    {
        const int rows    = (wid & 3) * 16;
        const int ntbase  = (wid >> 2) * 4;   // 4 tiles per warp
        wmma::fragment<wmma::accumulator, 16, 16, 16, float> acc[4];
#pragma unroll
        for (int t = 0; t < 4; t++) wmma::fill_fragment(acc[t], 0.f);
#pragma unroll
        for (int kt = 0; kt < 4; kt++) {
            wmma::fragment<wmma::matrix_a, 16, 16, 16, __half, wmma::row_major> af;
            wmma::load_matrix_sync(af, As + rows * KS2 + kt * 16, KS2);
#pragma unroll
            for (int t = 0; t < 4; t++) {
                wmma::fragment<wmma::matrix_b, 16, 16, 16, __half, wmma::row_major> bf;
                wmma::load_matrix_sync(bf, Bs + (kt * 16) * NS2 + (ntbase + t) * 16, NS2);
                wmma::mma_sync(acc[t], af, bf, acc[t]);
            }
        }
        __syncthreads();   // all As/Bs reads done before C overlay
#pragma unroll
        for (int t = 0; t < 4; t++)
            wmma::store_matrix_sync(Cs + rows * NSF + (ntbase + t) * 16, acc[t], NSF, wmma::mem_row_major);
    }
    __syncthreads();

    // ---- epilogue (N=128, H=4, C=32): 2 threads per row, threads < 128 ----
    if (threadIdx.x < 128) {
        const int row  = threadIdx.x & 63;
        const int half = threadIdx.x >> 6;
        const int n    = blk64 + row;
        if (n < N_NODES) {
            const int c0 = half * 64;
            const float* cr = Cs + row * NSF + c0;
            float sc[2], dc[2];
            sc[0] = sc[1] = dc[0] = dc[1] = 0.f;
#pragma unroll
            for (int i = 0; i < 64; i += 8) {
                float4 v0 = *reinterpret_cast<const float4*>(cr + i);
                float4 v1 = *reinterpret_cast<const float4*>(cr + i + 4);
                int hh = i / 32;
                sc[hh] += v0.x * as2[c0 + i + 0] + v0.y * as2[c0 + i + 1]
                        + v0.z * as2[c0 + i + 2] + v0.w * as2[c0 + i + 3]
                        + v1.x * as2[c0 + i + 4] + v1.y * as2[c0 + i + 5]
                        + v1.z * as2[c0 + i + 6] + v1.w * as2[c0 + i + 7];
                dc[hh] += v0.x * ad2[c0 + i + 0] + v0.y * ad2[c0 + i + 1]
                        + v0.z * ad2[c0 + i + 2] + v0.w * ad2[c0 + i + 3]
                        + v1.x * ad2[c0 + i + 4] + v1.y * ad2[c0 + i + 5]
                        + v1.z * ad2[c0 + i + 6] + v1.w * ad2[c0 + i + 7];
                __half2 p0 = __floats2half2_rn(v0.x, v0.y);
                __half2 p1 = __floats2half2_rn(v0.z, v0.w);
                __half2 p2 = __floats2half2_rn(v1.x, v1.y);
                __half2 p3 = __floats2half2_rn(v1.z, v1.w);
                uint4 pk;
                pk.x = *reinterpret_cast<unsigned*>(&p0);
                pk.y = *reinterpret_cast<unsigned*>(&p1);
                pk.z = *reinterpret_cast<unsigned*>(&p2);
                pk.w = *reinterpret_cast<unsigned*>(&p3);
                *reinterpret_cast<uint4*>(&hout2[(size_t)n * 128 + c0 + i]) = pk;
            }
            const int hb = half * 2;
            ssrc2[n * 4 + hb + 0] = sc[0];
            sdst2[n * 4 + hb + 0] = dc[0];
            ssrc2[n * 4 + hb + 1] = sc[1];
            sdst2[n * 4 + hb + 1] = dc[1];
        }
    }
}

// ================= FUSED: layer-2 agg (HC=128) + layer-3 scalar GEMM =================
// 256 threads. Phase 1: 8 warps x 8 nodes, MLP-2 agg, fp32 result into smem
// (stride 132 -> 2-way LDS conflicts). Phase 2: l3 GEMM (threads < 128).
__global__ void __launch_bounds__(256) fused_agg2_gemml3(
    const float* __restrict__ ssrc2, const float* __restrict__ sdst2,
    const __half* __restrict__ hbuf2, const float* __restrict__ b2,
    const float* __restrict__ W3, const float* __restrict__ as3,
    const float* __restrict__ ad3,
    __half* __restrict__ hout3, float* __restrict__ ssrc3, float* __restrict__ sdst3)
{
    constexpr int XS = 132;                 // floats per row (pad for banks)
    __shared__ __align__(16) float xs[64 * XS];   // 33792 B

    const int blk64 = blockIdx.x * 64;
    const int wid  = threadIdx.x >> 5;
    const int lane = threadIdx.x & 31;

    // ---- phase 1: agg (H=4, C=32, LPE=16, NSUB=2) ----
    {
        const int sub  = lane >> 4;        // 0..1
        const int cpos = lane & 15;        // 0..15
        const int j0   = cpos * 8;
        const int h    = j0 / 32;
        for (int r = 0; r < 8; r++) {
            const int lrow = wid * 8 + r;
            const int n    = blk64 + lrow;
            if (n >= N_NODES) break;

            const float sds = sdst2[n * 4 + h];
            float acc[8];
#pragma unroll
            for (int v = 0; v < 8; v++) acc[v] = 0.f;
            float den = 0.f;
            if (sub == 0) {
                float wself = __expf(lrelu(ssrc2[n * 4 + h] + sds));
                den = wself;
                float hv[8];
                ldh8f(&hbuf2[(size_t)n * 128 + j0], hv);
#pragma unroll
                for (int v = 0; v < 8; v++) acc[v] = wself * hv[v];
            }

            int e   = g_rowptr[n];
            int end = g_rowptr[n + 1];
            for (; e + 3 < end; e += 4) {
                int sA = g_srcsorted[e + sub];
                int sB = g_srcsorted[e + 2 + sub];
                float wA = __expf(lrelu(ssrc2[sA * 4 + h] + sds));
                float wB = __expf(lrelu(ssrc2[sB * 4 + h] + sds));
                float hA[8], hB[8];
                ldh8f(&hbuf2[(size_t)sA * 128 + j0], hA);
                ldh8f(&hbuf2[(size_t)sB * 128 + j0], hB);
#pragma unroll
                for (int v = 0; v < 8; v++) acc[v] += wA * hA[v] + wB * hB[v];
                den += wA + wB;
            }
            for (; e < end; e += 2) {
                int idx    = e + sub;
                bool valid = idx < end;
                int s = g_srcsorted[valid ? idx : e];
                float w = valid ? __expf(lrelu(ssrc2[s * 4 + h] + sds)) : 0.f;
                float hv[8];
                ldh8f(&hbuf2[(size_t)s * 128 + j0], hv);
#pragma unroll
                for (int v = 0; v < 8; v++) acc[v] += w * hv[v];
                den += w;
            }

#pragma unroll
            for (int v = 0; v < 8; v++) acc[v] += __shfl_xor_sync(0xffffffffu, acc[v], 16);
            den += __shfl_xor_sync(0xffffffffu, den, 16);

            if (sub == 0) {
                float inv = 1.f / den;
                float* po = &xs[lrow * XS + j0];
                float4 r0, r1;
                r0.x = fmaxf(acc[0] * inv + b2[j0 + 0], 0.f);
                r0.y = fmaxf(acc[1] * inv + b2[j0 + 1], 0.f);
                r0.z = fmaxf(acc[2] * inv + b2[j0 + 2], 0.f);
                r0.w = fmaxf(acc[3] * inv + b2[j0 + 3], 0.f);
                r1.x = fmaxf(acc[4] * inv + b2[j0 + 4], 0.f);
                r1.y = fmaxf(acc[5] * inv + b2[j0 + 5], 0.f);
                r1.z = fmaxf(acc[6] * inv + b2[j0 + 6], 0.f);
                r1.w = fmaxf(acc[7] * inv + b2[j0 + 7], 0.f);
                *reinterpret_cast<float4*>(po)     = r0;
                *reinterpret_cast<float4*>(po + 4) = r1;
            }
        }
    }
    __syncthreads();

    // ---- phase 2: layer-3 GEMM (K=128, HC=8, TPN=2), threads < 128 ----
    if (threadIdx.x < 128) {
        const int local = threadIdx.x >> 1;
        const int tj    = threadIdx.x & 1;
        const int j0g   = tj * 4;
        const int n     = blk64 + local;
        if (n < N_NODES) {
            const float* xr = &xs[local * XS];
            const float4* W4 = reinterpret_cast<const float4*>(W3);
            float a0 = 0.f, a1 = 0.f, a2 = 0.f, a3 = 0.f;
#pragma unroll 8
            for (int k = 0; k < 128; k++) {
                float xv = xr[k];
                float4 wv = W4[k * 2 + tj];
                a0 = fmaf(xv, wv.x, a0);
                a1 = fmaf(xv, wv.y, a1);
                a2 = fmaf(xv, wv.z, a2);
                a3 = fmaf(xv, wv.w, a3);
            }
            {
                __half2 lo = __floats2half2_rn(a0, a1);
                __half2 hi = __floats2half2_rn(a2, a3);
                uint2 pk;
                pk.x = *reinterpret_cast<unsigned*>(&lo);
                pk.y = *reinterpret_cast<unsigned*>(&hi);
                *reinterpret_cast<uint2*>(&hout3[(size_t)n * 8 + j0g]) = pk;
            }
            float vs = a0 * as3[j0g] + a1 * as3[j0g + 1] + a2 * as3[j0g + 2] + a3 * as3[j0g + 3];
            float vd = a0 * ad3[j0g] + a1 * ad3[j0g + 1] + a2 * ad3[j0g + 2] + a3 * ad3[j0g + 3];
            vs += __shfl_down_sync(0xffffffffu, vs, 1);
            vd += __shfl_down_sync(0xffffffffu, vd, 1);
            if (tj == 0) {
                ssrc3[n] = vs;
                sdst3[n] = vd;
            }
        }
    }
}

// ================= Layer 3: thread-per-node (HC=8), fused into pooling =================
__global__ void csr_agg_t8_pool(const float* __restrict__ ssrc, const float* __restrict__ sdst,
                                const __half* __restrict__ hbuf, const float* __restrict__ bias,
                                const int* __restrict__ batch)
{
    int n = blockIdx.x * blockDim.x + threadIdx.x;
    if (n >= N_NODES) return;
    const float sds   = sdst[n];
    const float wself = __expf(lrelu(ssrc[n] + sds));

    float a[8], hv[8];
    ldh8f(&hbuf[(size_t)n * 8], hv);
#pragma unroll
    for (int v = 0; v < 8; v++) a[v] = wself * hv[v];
    float den = wself;

    int e = g_rowptr[n], end = g_rowptr[n + 1];
    for (; e + 1 < end; e += 2) {
        int s0 = g_srcsorted[e], s1 = g_srcsorted[e + 1];
        float w0 = __expf(lrelu(ssrc[s0] + sds));
        float w1 = __expf(lrelu(ssrc[s1] + sds));
        float h0[8], h1[8];
        ldh8f(&hbuf[(size_t)s0 * 8], h0);
        ldh8f(&hbuf[(size_t)s1 * 8], h1);
#pragma unroll
        for (int v = 0; v < 8; v++) a[v] += w0 * h0[v] + w1 * h1[v];
        den += w0 + w1;
    }
    if (e < end) {
        int s = g_srcsorted[e];
        float w = __expf(lrelu(ssrc[s] + sds));
        ldh8f(&hbuf[(size_t)s * 8], hv);
#pragma unroll
        for (int v = 0; v < 8; v++) a[v] += w * hv[v];
        den += w;
    }
    float inv = 1.f / den;
    int g = batch[n];
    float* pp = &g_pool[g * 8];
#pragma unroll
    for (int v = 0; v < 8; v++) atomicAdd(pp + v, a[v] * inv + bias[v]);
    atomicAdd(&g_cnt[g], 1.f);
}

// ================= pooling epilogue =================
__global__ void pool_zero() {
    int i = blockIdx.x * blockDim.x + threadIdx.x;
    if (i < N_GRAPHS * 8) g_pool[i] = 0.f;
    if (i < N_GRAPHS)     g_cnt[i]  = 0.f;
}

__global__ void pool_out(float* __restrict__ out)
{
    int i = threadIdx.x;
    if (i < N_GRAPHS * 8) {
        float v = g_pool[i] / fmaxf(g_cnt[i / 8], 1.f);
        out[i] = 1.f / (1.f + expf(-v));
    }
}

// ================= launcher =================
static inline int cdiv(long a, long b) { return (int)((a + b - 1) / b); }

extern "C" void kernel_launch(void* const* d_in, const int* in_sizes, int n_in,
                              void* d_out, int out_size)
{
    const float* x     = (const float*)d_in[0];
    const int*   ei    = (const int*)  d_in[1];
    const int*   batch = (const int*)  d_in[2];
    const float* W1    = (const float*)d_in[3];
    const float* as1   = (const float*)d_in[4];
    const float* ad1   = (const float*)d_in[5];
    const float* b1    = (const float*)d_in[6];
    const float* W2    = (const float*)d_in[7];
    const float* as2   = (const float*)d_in[8];
    const float* ad2   = (const float*)d_in[9];
    const float* b2    = (const float*)d_in[10];
    const float* W3    = (const float*)d_in[11];
    const float* as3   = (const float*)d_in[12];
    const float* ad3   = (const float*)d_in[13];
    const float* b3    = (const float*)d_in[14];

    __half *bufH, *bufH2;
    float *ssrc, *sdst, *ssrc2, *sdst2;
    cudaGetSymbolAddress((void**)&bufH,  g_bufH);
    cudaGetSymbolAddress((void**)&bufH2, g_bufH2);
    cudaGetSymbolAddress((void**)&ssrc,  g_ssrc);
    cudaGetSymbolAddress((void**)&sdst,  g_sdst);
    cudaGetSymbolAddress((void**)&ssrc2, g_ssrc2);
    cudaGetSymbolAddress((void**)&sdst2, g_sdst2);

    static cudaStream_t s2 = nullptr;
    static cudaEvent_t evFork = nullptr, evJoin = nullptr;
    if (!s2) {
        cudaStreamCreateWithFlags(&s2, cudaStreamNonBlocking);
        cudaEventCreateWithFlags(&evFork, cudaEventDisableTiming);
        cudaEventCreateWithFlags(&evJoin, cudaEventDisableTiming);
    }

    const int T = 256;
    const int NB64 = cdiv(N_NODES, 64);   // 1563

    // ---------- fork: CSR build + pool_zero on side stream ----------
    cudaEventRecord(evFork, 0);
    cudaStreamWaitEvent(s2, evFork, 0);
    csr_zero_fill<<<cdiv(N_NODES, T), T, 0, s2>>>();
    csr_hist<<<cdiv(N_EDGES, T), T, 0, s2>>>(ei);
    csr_scan1<<<N_SCAN_BLKS, SCAN_BLK, 0, s2>>>();
    csr_scan2<<<1, 512, 0, s2>>>();
    csr_scan3<<<cdiv(N_NODES, T), T, 0, s2>>>();
    csr_scatter<<<cdiv(N_EDGES, T), T, 0, s2>>>(ei);
    pool_zero<<<3, T, 0, s2>>>();
    cudaEventRecord(evJoin, s2);

    // ---------- main stream: layer-1 GEMM (overlaps CSR build) ----------
    gemm_wmma<128, 64, 4, 16, float><<<NB64, 128>>>(x, W1, as1, ad1, bufH, ssrc, sdst);

    // ---------- join, then fused layers ----------
    cudaStreamWaitEvent(0, evJoin, 0);
    fused_agg1_gemm2<<<NB64, 256>>>(ssrc, sdst, bufH, b1, W2, as2, ad2, bufH2, ssrc2, sdst2);
    fused_agg2_gemml3<<<NB64, 256>>>(ssrc2, sdst2, bufH2, b2, W3, as3, ad3, bufH, ssrc, sdst);

    csr_agg_t8_pool<<<cdiv(N_NODES, T), T>>>(ssrc, sdst, bufH, b3, batch);
    pool_out<<<1, 512>>>((float*)d_out);
}